// round 1
// baseline (speedup 1.0000x reference)
#include <cuda_runtime.h>
#include <cstdint>
#include <cstddef>

// Problem dims (fixed by the dataset)
#define S_LEN 4096
#define BATCH 8
#define DDIM  1024
#define HDIM  1024
#define MROWS (BATCH * S_LEN)   // 32768

// Scratch: raw pre-activations k = x@Wz^T+bz and th = x@Wh^T+bh  (128 MB each)
__device__ float g_k[(size_t)MROWS * HDIM];
__device__ float g_t[(size_t)MROWS * HDIM];

// ---------------- packed f32x2 helpers ----------------
__device__ __forceinline__ unsigned long long dup2(float x) {
    unsigned long long r;
    asm("mov.b64 %0, {%1, %1};" : "=l"(r) : "f"(x));
    return r;
}
__device__ __forceinline__ unsigned long long pack2(float lo, float hi) {
    unsigned long long r;
    asm("mov.b64 %0, {%1, %2};" : "=l"(r) : "f"(lo), "f"(hi));
    return r;
}
__device__ __forceinline__ void fma2(unsigned long long& d,
                                     unsigned long long a,
                                     unsigned long long b) {
    asm("fma.rn.f32x2 %0, %1, %2, %0;" : "+l"(d) : "l"(a), "l"(b));
}
__device__ __forceinline__ float2 unpack2(unsigned long long v) {
    float lo, hi;
    asm("mov.b64 {%0, %1}, %2;" : "=f"(lo), "=f"(hi) : "l"(v));
    return make_float2(lo, hi);
}

// ---------------- fused dual GEMM ----------------
// C[m][n] = sum_d X[m][d] * W[n][d] + bias[n]
// grid.x in [0,16): x<8 -> (Wz,bz)->g_k tile n0=x*128 ; x>=8 -> (Wh,bh)->g_t
// grid.y: m tile. Consecutive blockIdx.x share the same X tile -> L2 reuse;
// both W matrices (8 MB) live in L2.
constexpr int BM = 128, BN = 128, BK = 16;
constexpr int PAD = 4;   // keeps float4 alignment (132*4 % 16 == 0), halves STS conflicts

__global__ void __launch_bounds__(256, 2)
gemm_dual(const float* __restrict__ X,
          const float* __restrict__ Wz, const float* __restrict__ bz,
          const float* __restrict__ Wh, const float* __restrict__ bh)
{
    __shared__ float As[BK][BM + PAD];
    __shared__ float Bs[BK][BN + PAD];

    const int  tid  = threadIdx.x;
    const int  m0   = blockIdx.y * BM;
    const bool is_z = (blockIdx.x < 8);
    const int  n0   = (is_z ? blockIdx.x : blockIdx.x - 8) * BN;

    const float* W    = is_z ? Wz : Wh;
    const float* bias = is_z ? bz : bh;
    float*       C    = is_z ? g_k : g_t;

    const int tx = tid & 15;   // 16 col-groups of 8
    const int ty = tid >> 4;   // 16 row-groups of 8

    const float* Ab = X + (size_t)m0 * DDIM;
    const float* Bb = W + (size_t)n0 * DDIM;

    unsigned long long acc[8][4];
#pragma unroll
    for (int i = 0; i < 8; i++)
#pragma unroll
        for (int p = 0; p < 4; p++) acc[i][p] = 0ull;

    // ---- load k-tile 0 into smem (transposed) ----
#pragma unroll
    for (int i = 0; i < 2; i++) {
        int l = tid + i * 256;
        int r = l >> 2, c = (l & 3) * 4;
        float4 va = *(const float4*)(Ab + (size_t)r * DDIM + c);
        float4 vb = *(const float4*)(Bb + (size_t)r * DDIM + c);
        As[c + 0][r] = va.x; As[c + 1][r] = va.y; As[c + 2][r] = va.z; As[c + 3][r] = va.w;
        Bs[c + 0][r] = vb.x; Bs[c + 1][r] = vb.y; Bs[c + 2][r] = vb.z; Bs[c + 3][r] = vb.w;
    }
    __syncthreads();

    for (int k0 = BK; k0 <= DDIM; k0 += BK) {
        float4 pa[2], pb[2];
        const bool more = (k0 < DDIM);
        if (more) {
#pragma unroll
            for (int i = 0; i < 2; i++) {
                int l = tid + i * 256;
                int r = l >> 2, c = (l & 3) * 4;
                pa[i] = *(const float4*)(Ab + (size_t)r * DDIM + k0 + c);
                pb[i] = *(const float4*)(Bb + (size_t)r * DDIM + k0 + c);
            }
        }
        // ---- compute on current smem tile ----
#pragma unroll
        for (int kk = 0; kk < BK; kk++) {
            float4 a0 = *(const float4*)&As[kk][ty * 8];
            float4 a1 = *(const float4*)&As[kk][ty * 8 + 4];
            float4 b0 = *(const float4*)&Bs[kk][tx * 8];
            float4 b1 = *(const float4*)&Bs[kk][tx * 8 + 4];
            unsigned long long ra[8] = {dup2(a0.x), dup2(a0.y), dup2(a0.z), dup2(a0.w),
                                        dup2(a1.x), dup2(a1.y), dup2(a1.z), dup2(a1.w)};
            unsigned long long rb[4] = {pack2(b0.x, b0.y), pack2(b0.z, b0.w),
                                        pack2(b1.x, b1.y), pack2(b1.z, b1.w)};
#pragma unroll
            for (int i = 0; i < 8; i++)
#pragma unroll
                for (int p = 0; p < 4; p++)
                    fma2(acc[i][p], ra[i], rb[p]);
        }
        if (more) {
            __syncthreads();
#pragma unroll
            for (int i = 0; i < 2; i++) {
                int l = tid + i * 256;
                int r = l >> 2, c = (l & 3) * 4;
                As[c + 0][r] = pa[i].x; As[c + 1][r] = pa[i].y; As[c + 2][r] = pa[i].z; As[c + 3][r] = pa[i].w;
                Bs[c + 0][r] = pb[i].x; Bs[c + 1][r] = pb[i].y; Bs[c + 2][r] = pb[i].z; Bs[c + 3][r] = pb[i].w;
            }
            __syncthreads();
        }
    }

    // ---- epilogue: + bias, store raw pre-activation ----
    float bv[8];
#pragma unroll
    for (int j = 0; j < 8; j++) bv[j] = bias[n0 + tx * 8 + j];
#pragma unroll
    for (int i = 0; i < 8; i++) {
        float o[8];
#pragma unroll
        for (int p = 0; p < 4; p++) {
            float2 u = unpack2(acc[i][p]);
            o[2 * p]     = u.x + bv[2 * p];
            o[2 * p + 1] = u.y + bv[2 * p + 1];
        }
        float* cp = C + (size_t)(m0 + ty * 8 + i) * HDIM + n0 + tx * 8;
        *(float4*)cp       = make_float4(o[0], o[1], o[2], o[3]);
        *(float4*)(cp + 4) = make_float4(o[4], o[5], o[6], o[7]);
    }
}

// ---------------- sequential scan ----------------
// h_t = (1-z_t) h_{t-1} + z_t g(th_t),  z = sigmoid(k),
// g(x) = x+0.5 (x>=0) else sigmoid(x);  h_0 = g(h0).
// Exactly equals the reference's log-space cumlogsumexp formulation.
__global__ void scan_kernel(const float* __restrict__ h0, float* __restrict__ out)
{
    const int b = blockIdx.y;
    const int h = blockIdx.x * 128 + threadIdx.x;
    const size_t base = ((size_t)b * S_LEN) * HDIM + h;
    const float* kp = g_k + base;
    const float* tp = g_t + base;
    float*       op = out + base;

    float x0 = h0[b * HDIM + h];
    float hc = (x0 >= 0.f) ? (x0 + 0.5f) : (1.f / (1.f + __expf(-x0)));

    for (int s0 = 0; s0 < S_LEN; s0 += 8) {
        float kk[8], tt[8];
#pragma unroll
        for (int j = 0; j < 8; j++) {              // batch loads: MLP=16/thread
            kk[j] = kp[(size_t)(s0 + j) * HDIM];
            tt[j] = tp[(size_t)(s0 + j) * HDIM];
        }
#pragma unroll
        for (int j = 0; j < 8; j++) {
            float z = 1.f / (1.f + __expf(-kk[j]));
            float t = tt[j];
            float g = (t >= 0.f) ? (t + 0.5f) : (1.f / (1.f + __expf(-t)));
            hc = fmaf(z, g - hc, hc);              // (1-z)h + z g
            op[(size_t)(s0 + j) * HDIM] = hc;
        }
    }
}

// ---------------- launch ----------------
extern "C" void kernel_launch(void* const* d_in, const int* in_sizes, int n_in,
                              void* d_out, int out_size)
{
    const float* x  = (const float*)d_in[0];
    const float* h0 = (const float*)d_in[1];
    const float* Wz = (const float*)d_in[2];
    const float* bz = (const float*)d_in[3];
    const float* Wh = (const float*)d_in[4];
    const float* bh = (const float*)d_in[5];
    float* out = (float*)d_out;

    dim3 ggrid(16, MROWS / BM);        // 16 n-jobs (8 z + 8 h) x 256 m-tiles
    gemm_dual<<<ggrid, 256>>>(x, Wz, bz, Wh, bh);

    dim3 sgrid(HDIM / 128, BATCH);     // 64 blocks x 128 threads, 1 channel/thread
    scan_kernel<<<sgrid, 128>>>(h0, out);
}

// round 3
// speedup vs baseline: 3.3540x; 3.3540x over previous
#include <cuda_runtime.h>
#include <cuda_bf16.h>
#include <cstdint>
#include <cstddef>

#define S_LEN 4096
#define BATCH 8
#define DDIM  1024
#define HDIM  1024
#define MROWS (BATCH * S_LEN)   // 32768
#define NCHUNK 32
#define CHLEN  128              // S_LEN / NCHUNK

// ---------------- scratch (device globals; no allocations allowed) ----------
__device__ float g_k[(size_t)MROWS * HDIM];                 // x@Wz^T+bz
__device__ float g_t[(size_t)MROWS * HDIM];                 // x@Wh^T+bh
__device__ __nv_bfloat16 g_xh[(size_t)MROWS * DDIM];
__device__ __nv_bfloat16 g_xl[(size_t)MROWS * DDIM];
__device__ __nv_bfloat16 g_wzh[(size_t)HDIM * DDIM];
__device__ __nv_bfloat16 g_wzl[(size_t)HDIM * DDIM];
__device__ __nv_bfloat16 g_whh[(size_t)HDIM * DDIM];
__device__ __nv_bfloat16 g_whl[(size_t)HDIM * DDIM];
__device__ float g_A[(size_t)BATCH * NCHUNK * HDIM];        // per-chunk prod(a)
__device__ float g_B[(size_t)BATCH * NCHUNK * HDIM];        // per-chunk h | h0=0
__device__ float g_S[(size_t)BATCH * NCHUNK * HDIM];        // per-chunk h_start

// ---------------- helpers ----------------------------------------------------
__device__ __forceinline__ uint32_t smem_u32(const void* p) {
    uint32_t a;
    asm("{ .reg .u64 t; cvta.to.shared.u64 t, %1; cvt.u32.u64 %0, t; }"
        : "=r"(a) : "l"(p));
    return a;
}
__device__ __forceinline__ void cp_async16(uint32_t dst, const void* src) {
    asm volatile("cp.async.cg.shared.global [%0], [%1], 16;"
                 :: "r"(dst), "l"(src) : "memory");
}
__device__ __forceinline__ void cp_commit() {
    asm volatile("cp.async.commit_group;" ::: "memory");
}
template <int N>
__device__ __forceinline__ void cp_wait() {
    asm volatile("cp.async.wait_group %0;" :: "n"(N) : "memory");
}
__device__ __forceinline__ void ldsm_x4(uint32_t& r0, uint32_t& r1,
                                        uint32_t& r2, uint32_t& r3, uint32_t addr) {
    asm volatile("ldmatrix.sync.aligned.m8n8.x4.shared.b16 {%0,%1,%2,%3}, [%4];"
                 : "=r"(r0), "=r"(r1), "=r"(r2), "=r"(r3) : "r"(addr));
}
__device__ __forceinline__ void mma16816(float* d, const uint32_t* a, const uint32_t* b) {
    asm volatile(
        "mma.sync.aligned.m16n8k16.row.col.f32.bf16.bf16.f32 "
        "{%0,%1,%2,%3}, {%4,%5,%6,%7}, {%8,%9}, {%0,%1,%2,%3};"
        : "+f"(d[0]), "+f"(d[1]), "+f"(d[2]), "+f"(d[3])
        : "r"(a[0]), "r"(a[1]), "r"(a[2]), "r"(a[3]), "r"(b[0]), "r"(b[1]));
}
__device__ __forceinline__ uint32_t sw128(uint32_t off) {
    return off ^ ((off >> 3) & 0x70);
}

// ---------------- fp32 -> bf16 hi/lo split -----------------------------------
__global__ void split_bf16(const float* __restrict__ src, int which, int n4)
{
    int i = blockIdx.x * blockDim.x + threadIdx.x;
    if (i >= n4) return;
    __nv_bfloat16* hi = (which == 0) ? g_xh : (which == 1) ? g_wzh : g_whh;
    __nv_bfloat16* lo = (which == 0) ? g_xl : (which == 1) ? g_wzl : g_whl;
    float4 v = ((const float4*)src)[i];
    float vv[4] = {v.x, v.y, v.z, v.w};
    __nv_bfloat16 h[4], l[4];
#pragma unroll
    for (int j = 0; j < 4; j++) {
        h[j] = __float2bfloat16(vv[j]);
        l[j] = __float2bfloat16(vv[j] - __bfloat162float(h[j]));
    }
    __nv_bfloat162* hp = (__nv_bfloat162*)(hi + (size_t)i * 4);
    __nv_bfloat162* lp = (__nv_bfloat162*)(lo + (size_t)i * 4);
    hp[0] = __nv_bfloat162(h[0], h[1]); hp[1] = __nv_bfloat162(h[2], h[3]);
    lp[0] = __nv_bfloat162(l[0], l[1]); lp[1] = __nv_bfloat162(l[2], l[3]);
}

// ---------------- HMMA GEMM: C = A'@B'^T + bias -------------------------------
// A' = [xh | xh | xl] (K_eff=3072), B' = [Whi | Wlo | Whi]
// CTA 128x128, 8 warps 2(m) x 4(n), warp tile 64x32. K-chunk 64 (128B/row, SW128).
#define KCH 64
#define NITER 48

__global__ void __launch_bounds__(256)
gemm_mma(const float* __restrict__ bz, const float* __restrict__ bh)
{
    __shared__ __align__(1024) uint8_t smem[2 * 32768];   // 2 stages x (A 16KB + B 16KB)

    const int tid = threadIdx.x, wid = tid >> 5, lane = tid & 31;
    const int wm = wid >> 2, wn = wid & 3;     // 2 x 4 warp grid
    const bool is_z = (blockIdx.x < 8);
    const int n0 = (is_z ? blockIdx.x : blockIdx.x - 8) * 128;
    const int m0 = blockIdx.y * 128;
    const __nv_bfloat16* Whi = is_z ? g_wzh : g_whh;
    const __nv_bfloat16* Wlo = is_z ? g_wzl : g_whl;
    const float* bias = is_z ? bz : bh;
    float* C = is_z ? g_k : g_t;

    const uint32_t sbase = smem_u32(smem);

    float acc[4][4][4];   // [mi][nj][frag]
#pragma unroll
    for (int i = 0; i < 4; i++)
#pragma unroll
        for (int j = 0; j < 4; j++)
#pragma unroll
            for (int f = 0; f < 4; f++) acc[i][j][f] = 0.f;

    // gmem source for chunk ch (0..47)
    auto srcA = [&](int ch) -> const __nv_bfloat16* {
        return ((ch >> 4) == 2) ? g_xl : g_xh;
    };
    auto srcB = [&](int ch) -> const __nv_bfloat16* {
        return ((ch >> 4) == 1) ? Wlo : Whi;
    };

    // issue cp.async loads for chunk ch into stage st
    auto issue = [&](int ch, int st) {
        const int kc = (ch & 15) * KCH;
        const __nv_bfloat16* Ap = srcA(ch);
        const __nv_bfloat16* Bp = srcB(ch);
        const uint32_t stb = sbase + st * 32768;
#pragma unroll
        for (int i = 0; i < 4; i++) {
            int s = tid + i * 256;              // 1024 slots of 16B per tile
            int row = s >> 3, kslot = s & 7;
            uint32_t off = sw128(row * 128 + kslot * 16);
            cp_async16(stb + off,
                       Ap + (size_t)(m0 + row) * DDIM + kc + kslot * 8);
            cp_async16(stb + 16384 + off,
                       Bp + (size_t)(n0 + row) * DDIM + kc + kslot * 8);
        }
        cp_commit();
    };

    issue(0, 0);

    for (int ch = 0; ch < NITER; ch++) {
        if (ch + 1 < NITER) issue(ch + 1, (ch + 1) & 1);
        if (ch + 1 < NITER) cp_wait<1>(); else cp_wait<0>();
        __syncthreads();

        const uint32_t stb = sbase + (ch & 1) * 32768;
        const uint32_t aB = stb;
        const uint32_t bB = stb + 16384;

#pragma unroll
        for (int ks = 0; ks < 4; ks++) {        // 4 x k16 per chunk
            uint32_t af[4][4], bf[2][4];
#pragma unroll
            for (int mi = 0; mi < 4; mi++) {
                int row = wm * 64 + mi * 16 + (lane & 15);
                uint32_t off = sw128(row * 128 + ks * 32 + (lane >> 4) * 16);
                ldsm_x4(af[mi][0], af[mi][1], af[mi][2], af[mi][3], aB + off);
            }
#pragma unroll
            for (int bj = 0; bj < 2; bj++) {
                int row = wn * 32 + bj * 16 + (lane & 7) + ((lane >> 4) & 1) * 8;
                uint32_t off = sw128(row * 128 + ks * 32 + ((lane >> 3) & 1) * 16);
                ldsm_x4(bf[bj][0], bf[bj][1], bf[bj][2], bf[bj][3], bB + off);
            }
#pragma unroll
            for (int mi = 0; mi < 4; mi++) {
#pragma unroll
                for (int bj = 0; bj < 2; bj++) {
                    mma16816(acc[mi][bj * 2],     af[mi], &bf[bj][0]);
                    mma16816(acc[mi][bj * 2 + 1], af[mi], &bf[bj][2]);
                }
            }
        }
        __syncthreads();
    }

    // epilogue: direct stores + bias
#pragma unroll
    for (int mi = 0; mi < 4; mi++) {
#pragma unroll
        for (int nj = 0; nj < 4; nj++) {
            int mrow = m0 + wm * 64 + mi * 16 + (lane >> 2);
            int ncol = n0 + wn * 32 + nj * 8 + (lane & 3) * 2;
            float2 bv = *(const float2*)(bias + ncol);
            float2 v0 = make_float2(acc[mi][nj][0] + bv.x, acc[mi][nj][1] + bv.y);
            float2 v1 = make_float2(acc[mi][nj][2] + bv.x, acc[mi][nj][3] + bv.y);
            *(float2*)(C + (size_t)mrow * HDIM + ncol) = v0;
            *(float2*)(C + (size_t)(mrow + 8) * HDIM + ncol) = v1;
        }
    }
}

// ---------------- scan: h_t = a_t h_{t-1} + b_t -------------------------------
__device__ __forceinline__ float sigf(float x) { return 1.f / (1.f + __expf(-x)); }
__device__ __forceinline__ float gfun(float x) { return (x >= 0.f) ? (x + 0.5f) : sigf(x); }

// pass 1: per-chunk (A = prod a, B = h with h_start=0)
__global__ void scan_p1()
{
    const int h  = blockIdx.x * 128 + threadIdx.x;
    const int ch = blockIdx.y;
    const int b  = blockIdx.z;
    const size_t base = ((size_t)(b * S_LEN + ch * CHLEN)) * HDIM + h;
    const float* kp = g_k + base;
    const float* tp = g_t + base;
    float A = 1.f, hB = 0.f;
    for (int s0 = 0; s0 < CHLEN; s0 += 4) {
        float kk[4], tt[4];
#pragma unroll
        for (int j = 0; j < 4; j++) {
            kk[j] = kp[(size_t)(s0 + j) * HDIM];
            tt[j] = tp[(size_t)(s0 + j) * HDIM];
        }
#pragma unroll
        for (int j = 0; j < 4; j++) {
            float z = sigf(kk[j]);
            float a = 1.f - z;
            hB = fmaf(a, hB, z * gfun(tt[j]));
            A *= a;
        }
    }
    const size_t ci = ((size_t)(b * NCHUNK + ch)) * HDIM + h;
    g_A[ci] = A;
    g_B[ci] = hB;
}

// pass 2: combine chunk states sequentially (32 steps per (b,h))
__global__ void scan_p2(const float* __restrict__ h0)
{
    const int h = blockIdx.x * 128 + threadIdx.x;
    const int b = blockIdx.y;
    float x0 = h0[b * HDIM + h];
    float hs = gfun(x0);
    for (int ch = 0; ch < NCHUNK; ch++) {
        const size_t ci = ((size_t)(b * NCHUNK + ch)) * HDIM + h;
        g_S[ci] = hs;
        hs = fmaf(g_A[ci], hs, g_B[ci]);
    }
}

// pass 3: re-run chunks from known start, emit outputs
__global__ void scan_p3(float* __restrict__ out)
{
    const int h  = blockIdx.x * 128 + threadIdx.x;
    const int ch = blockIdx.y;
    const int b  = blockIdx.z;
    const size_t base = ((size_t)(b * S_LEN + ch * CHLEN)) * HDIM + h;
    const float* kp = g_k + base;
    const float* tp = g_t + base;
    float* op = out + base;
    float hc = g_S[((size_t)(b * NCHUNK + ch)) * HDIM + h];
    for (int s0 = 0; s0 < CHLEN; s0 += 4) {
        float kk[4], tt[4];
#pragma unroll
        for (int j = 0; j < 4; j++) {
            kk[j] = kp[(size_t)(s0 + j) * HDIM];
            tt[j] = tp[(size_t)(s0 + j) * HDIM];
        }
#pragma unroll
        for (int j = 0; j < 4; j++) {
            float z = sigf(kk[j]);
            hc = fmaf(z, gfun(tt[j]) - hc, hc);
            op[(size_t)(s0 + j) * HDIM] = hc;
        }
    }
}

// ---------------- launch ------------------------------------------------------
extern "C" void kernel_launch(void* const* d_in, const int* in_sizes, int n_in,
                              void* d_out, int out_size)
{
    const float* x  = (const float*)d_in[0];
    const float* h0 = (const float*)d_in[1];
    const float* Wz = (const float*)d_in[2];
    const float* bz = (const float*)d_in[3];
    const float* Wh = (const float*)d_in[4];
    const float* bh = (const float*)d_in[5];
    float* out = (float*)d_out;

    split_bf16<<<(MROWS * DDIM / 4 + 255) / 256, 256>>>(x, 0, MROWS * DDIM / 4);
    split_bf16<<<(HDIM * DDIM / 4 + 255) / 256, 256>>>(Wz, 1, HDIM * DDIM / 4);
    split_bf16<<<(HDIM * DDIM / 4 + 255) / 256, 256>>>(Wh, 2, HDIM * DDIM / 4);

    dim3 ggrid(16, MROWS / 128);
    gemm_mma<<<ggrid, 256>>>(bz, bh);

    dim3 p1grid(HDIM / 128, NCHUNK, BATCH);
    scan_p1<<<p1grid, 128>>>();
    dim3 p2grid(HDIM / 128, BATCH);
    scan_p2<<<p2grid, 128>>>(h0);
    scan_p3<<<p1grid, 128>>>(out);
}